// round 3
// baseline (speedup 1.0000x reference)
#include <cuda_runtime.h>

// BarlowTwinsLoss: e_q [16384,2048] f32, tau [16384,2048] f32, row-major.
// loss = sum_d (1 - clip(corr_d, -1+eps, 1-eps))^2, corr from column-normalized
// (ddof=1) features. Pure streaming reduction: 256 MB mandatory HBM reads.
//
// R3: SINGLE fused kernel. 512 blocks stream sufficient statistics into a
// 320 KB partial buffer; the last block to finish (atomic ticket) performs the
// fixed-order fp32 finalize (deterministic, hits hot L2). No fp64 anywhere.

#define NROWS 16384
#define NCOLS 2048
#define ROW_CHUNKS 8                                 // blockIdx.y
#define ROWS_PER_CHUNK (NROWS / ROW_CHUNKS)          // 2048
#define SUBCHUNKS 8                                  // threadIdx.y
#define ROWS_PER_THREAD (ROWS_PER_CHUNK / SUBCHUNKS) // 256
#define COLS_PER_BLOCK 32                            // threadIdx.x
#define COL_BLOCKS (NCOLS / COLS_PER_BLOCK)          // 64
#define NBLOCKS (COL_BLOCKS * ROW_CHUNKS)            // 512

// 5 stats x 8 rowchunks x 2048 cols x 4B = 320 KB static scratch
__device__ float g_partial[5][ROW_CHUNKS][NCOLS];
__device__ unsigned int g_ticket;   // zero-initialized; reset by last block

__global__ void __launch_bounds__(256)
barlow_kernel(const float* __restrict__ e, const float* __restrict__ t,
              float* __restrict__ out)
{
    const int colbase = blockIdx.x * COLS_PER_BLOCK;
    const int col     = colbase + threadIdx.x;
    const size_t row0 = (size_t)blockIdx.y * ROWS_PER_CHUNK
                      + (size_t)threadIdx.y * ROWS_PER_THREAD;

    const float* __restrict__ pe = e + row0 * NCOLS + col;
    const float* __restrict__ pt = t + row0 * NCOLS + col;

    float se = 0.f, st = 0.f, ee = 0.f, tt = 0.f, et = 0.f;

    #pragma unroll 8
    for (int r = 0; r < ROWS_PER_THREAD; ++r) {
        float a = __ldcs(pe + (size_t)r * NCOLS);    // read-once: evict-first
        float b = __ldcs(pt + (size_t)r * NCOLS);
        se += a;
        st += b;
        ee = fmaf(a, a, ee);
        tt = fmaf(b, b, tt);
        et = fmaf(a, b, et);
    }

    __shared__ float sh[5][SUBCHUNKS][COLS_PER_BLOCK + 1];
    sh[0][threadIdx.y][threadIdx.x] = se;
    sh[1][threadIdx.y][threadIdx.x] = st;
    sh[2][threadIdx.y][threadIdx.x] = ee;
    sh[3][threadIdx.y][threadIdx.x] = tt;
    sh[4][threadIdx.y][threadIdx.x] = et;
    __syncthreads();

    const int tid = threadIdx.y * COLS_PER_BLOCK + threadIdx.x;

    // 160 threads: (stat s, col tx). Fixed-order sum over 8 subchunks.
    if (tid < 5 * COLS_PER_BLOCK) {
        const int s  = tid >> 5;
        const int tx = tid & 31;
        float acc = 0.f;
        #pragma unroll
        for (int k = 0; k < SUBCHUNKS; ++k)
            acc += sh[s][k][tx];
        g_partial[s][blockIdx.y][colbase + tx] = acc;
    }

    // ---- last-block finalize -------------------------------------------
    __threadfence();                 // publish partials before the ticket
    __syncthreads();

    __shared__ unsigned int s_last;
    if (tid == 0)
        s_last = (atomicAdd(&g_ticket, 1u) == NBLOCKS - 1u) ? 1u : 0u;
    __syncthreads();
    if (!s_last) return;

    __threadfence();                 // acquire: order partial reads after ticket

    const float Nf   = 16384.0f;
    const float EPSf = 1e-9f;
    float loss = 0.f;

    // 256 threads, 8 cols each; reads coalesced, hot in L2.
    for (int c0 = 0; c0 < NCOLS; c0 += 256) {
        const int ccol = c0 + tid;

        float S[5];
        #pragma unroll
        for (int s = 0; s < 5; ++s) {
            float acc = 0.f;
            #pragma unroll
            for (int rb = 0; rb < ROW_CHUNKS; ++rb)
                acc += g_partial[s][rb][ccol];
            S[s] = acc;
        }

        const float Se = S[0], St = S[1], See = S[2], Stt = S[3], Set = S[4];
        const float vare = (See - Se * Se / Nf) / (Nf - 1.0f);
        const float vart = (Stt - St * St / Nf) / (Nf - 1.0f);
        const float stde = fmaxf(sqrtf(fmaxf(vare, 0.f)), EPSf);
        const float stdt = fmaxf(sqrtf(fmaxf(vart, 0.f)), EPSf);
        const float cross = Set - Se * St / Nf;

        float c = cross / (stde * stdt) / (Nf + EPSf);
        c = fminf(fmaxf(c, -1.0f + EPSf), 1.0f - EPSf);
        const float d = 1.0f - c;
        loss = fmaf(d, d, loss);
    }

    __shared__ float red[256];
    red[tid] = loss;
    __syncthreads();
    #pragma unroll
    for (int s = 128; s > 0; s >>= 1) {
        if (tid < s) red[tid] += red[tid + s];
        __syncthreads();
    }
    if (tid == 0) {
        out[0] = red[0];
        g_ticket = 0;                // reset for next graph replay
    }
}

// ---------------------------------------------------------------------------
extern "C" void kernel_launch(void* const* d_in, const int* in_sizes, int n_in,
                              void* d_out, int out_size)
{
    const float* e_q = (const float*)d_in[0];
    const float* tau = (const float*)d_in[1];
    float* out = (float*)d_out;

    dim3 block1(COLS_PER_BLOCK, SUBCHUNKS);       // 32 x 8 = 256
    dim3 grid1(COL_BLOCKS, ROW_CHUNKS);           // 64 x 8 = 512 blocks
    barlow_kernel<<<grid1, block1>>>(e_q, tau, out);
}